// round 3
// baseline (speedup 1.0000x reference)
#include <cuda_runtime.h>
#include <math.h>

#define NN 100000
#define EE 3200000
#define HID 16
#define NCLS 10
#define KK 50000
#define SSIZE 131072
#define TILE 4096

typedef unsigned long long ull;

__device__ float  d_h0[NN * HID];
__device__ float  d_h[NN * HID];
__device__ int    d_cnt[NN];
__device__ int    d_rowptr[NN + 1];
__device__ int    d_cursor[NN];
__device__ float  d_dinv[NN];
__device__ int    d_csr[EE];
__device__ double d_spart[NN];
__device__ double d_t2[NN];
__device__ float  d_s[NN];
__device__ ull    d_keys[SSIZE];
__device__ int    d_nidx[NN];
__device__ int    d_perm[KK];
__device__ float  d_h2[KK * NCLS];
__device__ float  d_dinv2[KK];

__global__ void kinit() {
    int i = blockIdx.x * blockDim.x + threadIdx.x;
    if (i < SSIZE) d_keys[i] = 0ull;
    if (i < NN) { d_cnt[i] = 0; d_nidx[i] = -1; }
}

// h0 = x @ w1, double accumulation. 16 rows x 16 cols per 256-thread block.
__global__ void kgemm1(const float* __restrict__ x, const float* __restrict__ w1) {
    __shared__ __align__(16) float xs[16 * 128];
    __shared__ float ws[128 * 16];
    int t = threadIdx.x;
    for (int i = t; i < 2048; i += 256) ws[i] = w1[i];
    const float4* xg4 = (const float4*)(x + (size_t)blockIdx.x * 16 * 128);
    float4* xs4 = (float4*)xs;
    for (int i = t; i < 512; i += 256) xs4[i] = xg4[i];
    __syncthreads();
    int r = t >> 4, c = t & 15;
    double acc = 0.0;
#pragma unroll
    for (int k = 0; k < 128; k++)
        acc += (double)xs[r * 128 + k] * (double)ws[k * 16 + c];
    d_h0[(size_t)(blockIdx.x * 16 + r) * HID + c] = (float)acc;
}

__global__ void kcount(const int* __restrict__ ei) {
    int e = blockIdx.x * blockDim.x + threadIdx.x;
    if (e < EE) atomicAdd(&d_cnt[ei[EE + e]], 1);
}

// single-block exclusive scan over counts; also deg->dinv
__global__ void kscan() {
    __shared__ int warp_s[32];
    __shared__ int carry_s;
    int t = threadIdx.x, lane = t & 31, wd = t >> 5;
    if (t == 0) carry_s = 0;
    __syncthreads();
    for (int base = 0; base < NN; base += 1024) {
        int i = base + t;
        int v = (i < NN) ? d_cnt[i] : 0;
        int xv = v;
#pragma unroll
        for (int o = 1; o < 32; o <<= 1) {
            int y = __shfl_up_sync(0xFFFFFFFFu, xv, o);
            if (lane >= o) xv += y;
        }
        if (lane == 31) warp_s[wd] = xv;
        __syncthreads();
        if (wd == 0) {
            int s2 = warp_s[lane];
#pragma unroll
            for (int o = 1; o < 32; o <<= 1) {
                int y = __shfl_up_sync(0xFFFFFFFFu, s2, o);
                if (lane >= o) s2 += y;
            }
            warp_s[lane] = s2;
        }
        __syncthreads();
        int excl = xv - v + (wd > 0 ? warp_s[wd - 1] : 0) + carry_s;
        if (i < NN) {
            d_rowptr[i] = excl;
            d_cursor[i] = excl;
            d_dinv[i] = (float)(1.0 / sqrt((double)(v + 1)));
        }
        __syncthreads();
        if (t == 0) carry_s += warp_s[31];
        __syncthreads();
    }
    if (t == 0) d_rowptr[NN] = carry_s;
}

__global__ void kscatter(const int* __restrict__ ei) {
    int e = blockIdx.x * blockDim.x + threadIdx.x;
    if (e < EE) {
        int s = ei[e];
        int d = ei[EE + e];
        d_csr[atomicAdd(&d_cursor[d], 1)] = s;
    }
}

// conv1 (+relu) with double accumulation; also score linear terms
__global__ void kconv1(const float* __restrict__ b1, const float* __restrict__ pw1,
                       const float* __restrict__ pw2, const float* __restrict__ pb) {
    int gw = (blockIdx.x * blockDim.x + threadIdx.x) >> 5;
    if (gw >= NN) return;
    int lane = threadIdx.x & 31, half = lane >> 4, ch = lane & 15;
    int st = d_rowptr[gw], en = d_rowptr[gw + 1];
    double a = 0.0;
    for (int e = st + half; e < en; e += 2) {
        int sN = d_csr[e];
        a += (double)d_dinv[sN] * (double)d_h0[sN * HID + ch];
    }
    a += __shfl_xor_sync(0xFFFFFFFFu, a, 16);
    double degf = (double)(en - st + 1);
    double hvd = (double)d_dinv[gw] * a
               + (double)d_h0[gw * HID + ch] / degf + (double)b1[ch];
    float hv = fmaxf((float)hvd, 0.f);
    if (half == 0) d_h[gw * HID + ch] = hv;
    double u1 = (double)hv * (double)pw1[ch];
    double u2 = (double)hv * (double)pw2[ch];
#pragma unroll
    for (int o = 8; o; o >>= 1) {
        u1 += __shfl_xor_sync(0xFFFFFFFFu, u1, o);
        u2 += __shfl_xor_sync(0xFFFFFFFFu, u2, o);
    }
    if (lane == 0) { d_spart[gw] = u1 + (double)pb[0]; d_t2[gw] = u2; }
}

// score = spart + sum_{in-neighbors} t2 ; build sort key
__global__ void kpool() {
    int gw = (blockIdx.x * blockDim.x + threadIdx.x) >> 5;
    if (gw >= NN) return;
    int lane = threadIdx.x & 31;
    int st = d_rowptr[gw], en = d_rowptr[gw + 1];
    double sum = 0.0;
    for (int e = st + lane; e < en; e += 32) sum += d_t2[d_csr[e]];
#pragma unroll
    for (int o = 16; o; o >>= 1) sum += __shfl_xor_sync(0xFFFFFFFFu, sum, o);
    if (lane == 0) {
        float sv = (float)(d_spart[gw] + sum);
        d_s[gw] = sv;
        unsigned u = __float_as_uint(sv);
        u = (u & 0x80000000u) ? ~u : (u | 0x80000000u);
        d_keys[gw] = ((ull)u << 32) | (ull)(~(unsigned)gw);
    }
}

// bitonic sort, descending, SSIZE unique keys
__global__ void __launch_bounds__(1024) ksort_init() {
    __shared__ ull sk[TILE];
    int base = blockIdx.x * TILE;
    for (int i = threadIdx.x; i < TILE; i += 1024) sk[i] = d_keys[base + i];
    __syncthreads();
    for (int k = 2; k <= TILE; k <<= 1)
        for (int j = k >> 1; j > 0; j >>= 1) {
            for (int i = threadIdx.x; i < TILE; i += 1024) {
                int p = i ^ j;
                if (p > i) {
                    bool desc = (((base + i) & k) == 0);
                    ull A = sk[i], B = sk[p];
                    if ((A < B) == desc) { sk[i] = B; sk[p] = A; }
                }
            }
            __syncthreads();
        }
    for (int i = threadIdx.x; i < TILE; i += 1024) d_keys[base + i] = sk[i];
}

__global__ void ksort_global(int j, int k) {
    int i = blockIdx.x * blockDim.x + threadIdx.x;
    int p = i ^ j;
    if (p > i && p < SSIZE) {
        bool desc = ((i & k) == 0);
        ull A = d_keys[i], B = d_keys[p];
        if ((A < B) == desc) { d_keys[i] = B; d_keys[p] = A; }
    }
}

__global__ void __launch_bounds__(1024) ksort_merge(int k) {
    __shared__ ull sk[TILE];
    int base = blockIdx.x * TILE;
    for (int i = threadIdx.x; i < TILE; i += 1024) sk[i] = d_keys[base + i];
    __syncthreads();
    for (int j = TILE >> 1; j > 0; j >>= 1) {
        for (int i = threadIdx.x; i < TILE; i += 1024) {
            int p = i ^ j;
            if (p > i) {
                bool desc = (((base + i) & k) == 0);
                ull A = sk[i], B = sk[p];
                if ((A < B) == desc) { sk[i] = B; sk[p] = A; }
            }
        }
        __syncthreads();
    }
    for (int i = threadIdx.x; i < TILE; i += 1024) d_keys[base + i] = sk[i];
}

// top-K select: perm, inverse map, h2 = tanh(s) * (h @ w2)
__global__ void kselect(const float* __restrict__ w2) {
    int r = (blockIdx.x * blockDim.x + threadIdx.x) >> 5;
    if (r >= KK) return;
    int lane = threadIdx.x & 31;
    ull key = d_keys[r];
    int idx = (int)(~(unsigned)(key & 0xFFFFFFFFull));
    if (lane == 0) { d_nidx[idx] = r; d_perm[r] = idx; }
    if (lane < NCLS) {
        float th = tanhf(d_s[idx]);
        float acc = 0.f;
#pragma unroll
        for (int j = 0; j < HID; j++)
            acc += d_h[idx * HID + j] * w2[j * NCLS + lane];
        d_h2[r * NCLS + lane] = th * acc;
    }
}

// surviving-degree of kept nodes; pre-scale h2 rows by dinv2
__global__ void kdeg2() {
    int r = (blockIdx.x * blockDim.x + threadIdx.x) >> 5;
    if (r >= KK) return;
    int lane = threadIdx.x & 31;
    int i = d_perm[r];
    int st = d_rowptr[i], en = d_rowptr[i + 1];
    int cnt = 0;
    for (int e = st + lane; e < en; e += 32) cnt += (d_nidx[d_csr[e]] >= 0);
#pragma unroll
    for (int o = 16; o; o >>= 1) cnt += __shfl_xor_sync(0xFFFFFFFFu, cnt, o);
    float d2 = (float)(1.0 / sqrt((double)(cnt + 1)));
    if (lane == 0) d_dinv2[r] = d2;
    if (lane < NCLS) d_h2[r * NCLS + lane] *= d2;
}

// conv2 gather + relu + log_softmax
__global__ void kconv2(const float* __restrict__ b2, float* __restrict__ out) {
    int r = (blockIdx.x * blockDim.x + threadIdx.x) >> 5;
    if (r >= KK) return;
    int lane = threadIdx.x & 31;
    bool act = lane < NCLS;
    int i = d_perm[r];
    int st = d_rowptr[i], en = d_rowptr[i + 1];
    float acc = 0.f;
    for (int e = st; e < en; e++) {
        int n0 = d_nidx[d_csr[e]];
        if (act && n0 >= 0) acc += d_h2[n0 * NCLS + lane];
    }
    float d2 = d_dinv2[r];
    float v = act ? fmaxf(d2 * (acc + d_h2[r * NCLS + lane]) + b2[lane], 0.f)
                  : -1e30f;
    float m = v;
#pragma unroll
    for (int o = 8; o; o >>= 1)
        m = fmaxf(m, __shfl_xor_sync(0xFFFFFFFFu, m, o, 16));
    float ex = act ? expf(v - m) : 0.f;
#pragma unroll
    for (int o = 8; o; o >>= 1)
        ex += __shfl_xor_sync(0xFFFFFFFFu, ex, o, 16);
    if (act) out[r * NCLS + lane] = v - m - logf(ex);
}

extern "C" void kernel_launch(void* const* d_in, const int* in_sizes, int n_in,
                              void* d_out, int out_size) {
    const float* x  = (const float*)d_in[0];
    const int*   ei = (const int*)d_in[1];
    const float* w1 = (const float*)d_in[2];
    const float* b1 = (const float*)d_in[3];
    const float* pw1 = (const float*)d_in[4];
    const float* pw2 = (const float*)d_in[5];
    const float* pb = (const float*)d_in[6];
    const float* w2 = (const float*)d_in[7];
    const float* b2 = (const float*)d_in[8];
    float* out = (float*)d_out;

    kinit<<<SSIZE / 256, 256>>>();
    kgemm1<<<NN / 16, 256>>>(x, w1);
    kcount<<<EE / 256, 256>>>(ei);
    kscan<<<1, 1024>>>();
    kscatter<<<EE / 256, 256>>>(ei);
    kconv1<<<NN * 32 / 256, 256>>>(b1, pw1, pw2, pb);
    kpool<<<NN * 32 / 256, 256>>>();

    ksort_init<<<SSIZE / TILE, 1024>>>();
    for (int k = TILE * 2; k <= SSIZE; k <<= 1) {
        for (int j = k >> 1; j >= TILE; j >>= 1)
            ksort_global<<<SSIZE / 256, 256>>>(j, k);
        ksort_merge<<<SSIZE / TILE, 1024>>>(k);
    }

    kselect<<<KK * 32 / 256, 256>>>(w2);
    kdeg2<<<KK * 32 / 256, 256>>>();
    kconv2<<<KK * 32 / 256, 256>>>(b2, out);
}

// round 4
// speedup vs baseline: 1.2883x; 1.2883x over previous
#include <cuda_runtime.h>
#include <math.h>

#define NN 100000
#define EE 3200000
#define HID 16
#define NCLS 10
#define KK 50000
#define SSIZE 131072
#define TILE 4096
#define SBLK 1024
#define NBLK 98   // ceil(100000/1024)

typedef unsigned long long ull;

__device__ float  d_h0[NN * HID];
__device__ float  d_h[NN * HID];
__device__ int    d_cnt[NN];
__device__ int    d_rowptr[NN + 1];
__device__ int    d_cursor[NN];
__device__ float  d_dinv[NN];
__device__ int    d_csr[EE];
__device__ double d_spart[NN];
__device__ double d_t2[NN];
__device__ float  d_s[NN];
__device__ ull    d_keys[SSIZE];
__device__ int    d_nidx[NN];
__device__ int    d_perm[KK];
__device__ float  d_h2[KK * NCLS];
__device__ float  d_dinv2[KK];
__device__ int    d_bsum[NBLK];
__device__ int    d_boff[NBLK];

__global__ void kinit() {
    int i = blockIdx.x * blockDim.x + threadIdx.x;
    if (i < SSIZE) d_keys[i] = 0ull;
    if (i < NN) { d_cnt[i] = 0; d_nidx[i] = -1; }
}

// h0 = x @ w1, double accumulation. 16 rows x 16 cols per 256-thread block.
__global__ void kgemm1(const float* __restrict__ x, const float* __restrict__ w1) {
    __shared__ __align__(16) float xs[16 * 128];
    __shared__ float ws[128 * 16];
    int t = threadIdx.x;
    for (int i = t; i < 2048; i += 256) ws[i] = w1[i];
    const float4* xg4 = (const float4*)(x + (size_t)blockIdx.x * 16 * 128);
    float4* xs4 = (float4*)xs;
    for (int i = t; i < 512; i += 256) xs4[i] = xg4[i];
    __syncthreads();
    int r = t >> 4, c = t & 15;
    double acc = 0.0;
#pragma unroll
    for (int k = 0; k < 128; k++)
        acc += (double)xs[r * 128 + k] * (double)ws[k * 16 + c];
    d_h0[(size_t)(blockIdx.x * 16 + r) * HID + c] = (float)acc;
}

__global__ void kcount(const int* __restrict__ ei) {
    int e = blockIdx.x * blockDim.x + threadIdx.x;
    if (e < EE) atomicAdd(&d_cnt[ei[EE + e]], 1);
}

// ---- decoupled scan: A) block sums  B) scan block sums  C) local scan+offset
__global__ void __launch_bounds__(SBLK) kscanA() {
    __shared__ int ws[32];
    int i = blockIdx.x * SBLK + threadIdx.x;
    int lane = threadIdx.x & 31, wd = threadIdx.x >> 5;
    int v = (i < NN) ? d_cnt[i] : 0;
    int s = v;
#pragma unroll
    for (int o = 16; o; o >>= 1) s += __shfl_xor_sync(0xFFFFFFFFu, s, o);
    if (lane == 0) ws[wd] = s;
    __syncthreads();
    if (wd == 0) {
        int s2 = ws[lane];
#pragma unroll
        for (int o = 16; o; o >>= 1) s2 += __shfl_xor_sync(0xFFFFFFFFu, s2, o);
        if (lane == 0) d_bsum[blockIdx.x] = s2;
    }
}

__global__ void kscanB() {
    __shared__ int sm[128];
    int t = threadIdx.x;
    int v = (t < NBLK) ? d_bsum[t] : 0;
    sm[t] = v;
    __syncthreads();
    for (int o = 1; o < 128; o <<= 1) {
        int y = (t >= o) ? sm[t - o] : 0;
        __syncthreads();
        sm[t] += y;
        __syncthreads();
    }
    if (t < NBLK) d_boff[t] = sm[t] - v;
    if (t == NBLK - 1) d_rowptr[NN] = sm[t];
}

__global__ void __launch_bounds__(SBLK) kscanC() {
    __shared__ int ws[32];
    int i = blockIdx.x * SBLK + threadIdx.x;
    int lane = threadIdx.x & 31, wd = threadIdx.x >> 5;
    int v = (i < NN) ? d_cnt[i] : 0;
    int xv = v;
#pragma unroll
    for (int o = 1; o < 32; o <<= 1) {
        int y = __shfl_up_sync(0xFFFFFFFFu, xv, o);
        if (lane >= o) xv += y;
    }
    if (lane == 31) ws[wd] = xv;
    __syncthreads();
    if (wd == 0) {
        int s2 = ws[lane];
#pragma unroll
        for (int o = 1; o < 32; o <<= 1) {
            int y = __shfl_up_sync(0xFFFFFFFFu, s2, o);
            if (lane >= o) s2 += y;
        }
        ws[lane] = s2;
    }
    __syncthreads();
    int excl = xv - v + (wd > 0 ? ws[wd - 1] : 0) + d_boff[blockIdx.x];
    if (i < NN) {
        d_rowptr[i] = excl;
        d_cursor[i] = excl;
        d_dinv[i] = (float)(1.0 / sqrt((double)(v + 1)));
    }
}

__global__ void kscatter(const int* __restrict__ ei) {
    int e = blockIdx.x * blockDim.x + threadIdx.x;
    if (e < EE) {
        int s = ei[e];
        int d = ei[EE + e];
        d_csr[atomicAdd(&d_cursor[d], 1)] = s;
    }
}

// conv1 (+relu) fp64 accumulation, 4-way unrolled gathers; score linear terms
__global__ void kconv1(const float* __restrict__ b1, const float* __restrict__ pw1,
                       const float* __restrict__ pw2, const float* __restrict__ pb) {
    int gw = (blockIdx.x * blockDim.x + threadIdx.x) >> 5;
    if (gw >= NN) return;
    int lane = threadIdx.x & 31, half = lane >> 4, ch = lane & 15;
    int st = d_rowptr[gw], en = d_rowptr[gw + 1];
    double a0 = 0.0, a1 = 0.0, a2 = 0.0, a3 = 0.0;
    int e = st + half;
    for (; e + 6 < en; e += 8) {
        int s0 = d_csr[e], s1 = d_csr[e + 2], s2 = d_csr[e + 4], s3 = d_csr[e + 6];
        a0 += (double)d_dinv[s0] * (double)d_h0[s0 * HID + ch];
        a1 += (double)d_dinv[s1] * (double)d_h0[s1 * HID + ch];
        a2 += (double)d_dinv[s2] * (double)d_h0[s2 * HID + ch];
        a3 += (double)d_dinv[s3] * (double)d_h0[s3 * HID + ch];
    }
    for (; e < en; e += 2) {
        int s0 = d_csr[e];
        a0 += (double)d_dinv[s0] * (double)d_h0[s0 * HID + ch];
    }
    double a = (a0 + a1) + (a2 + a3);
    a += __shfl_xor_sync(0xFFFFFFFFu, a, 16);
    double degf = (double)(en - st + 1);
    double hvd = (double)d_dinv[gw] * a
               + (double)d_h0[gw * HID + ch] / degf + (double)b1[ch];
    float hv = fmaxf((float)hvd, 0.f);
    if (half == 0) d_h[gw * HID + ch] = hv;
    double u1 = (double)hv * (double)pw1[ch];
    double u2 = (double)hv * (double)pw2[ch];
#pragma unroll
    for (int o = 8; o; o >>= 1) {
        u1 += __shfl_xor_sync(0xFFFFFFFFu, u1, o);
        u2 += __shfl_xor_sync(0xFFFFFFFFu, u2, o);
    }
    if (lane == 0) { d_spart[gw] = u1 + (double)pb[0]; d_t2[gw] = u2; }
}

// score = spart + sum_{in-neighbors} t2 ; build sort key
__global__ void kpool() {
    int gw = (blockIdx.x * blockDim.x + threadIdx.x) >> 5;
    if (gw >= NN) return;
    int lane = threadIdx.x & 31;
    int st = d_rowptr[gw], en = d_rowptr[gw + 1];
    double sum = 0.0;
    for (int e = st + lane; e < en; e += 32) sum += d_t2[d_csr[e]];
#pragma unroll
    for (int o = 16; o; o >>= 1) sum += __shfl_xor_sync(0xFFFFFFFFu, sum, o);
    if (lane == 0) {
        float sv = (float)(d_spart[gw] + sum);
        d_s[gw] = sv;
        unsigned u = __float_as_uint(sv);
        u = (u & 0x80000000u) ? ~u : (u | 0x80000000u);
        d_keys[gw] = ((ull)u << 32) | (ull)(~(unsigned)gw);
    }
}

// bitonic sort, descending, SSIZE unique keys
__global__ void __launch_bounds__(1024) ksort_init() {
    __shared__ ull sk[TILE];
    int base = blockIdx.x * TILE;
    for (int i = threadIdx.x; i < TILE; i += 1024) sk[i] = d_keys[base + i];
    __syncthreads();
    for (int k = 2; k <= TILE; k <<= 1)
        for (int j = k >> 1; j > 0; j >>= 1) {
            for (int i = threadIdx.x; i < TILE; i += 1024) {
                int p = i ^ j;
                if (p > i) {
                    bool desc = (((base + i) & k) == 0);
                    ull A = sk[i], B = sk[p];
                    if ((A < B) == desc) { sk[i] = B; sk[p] = A; }
                }
            }
            __syncthreads();
        }
    for (int i = threadIdx.x; i < TILE; i += 1024) d_keys[base + i] = sk[i];
}

__global__ void ksort_global(int j, int k) {
    int i = blockIdx.x * blockDim.x + threadIdx.x;
    int p = i ^ j;
    if (p > i && p < SSIZE) {
        bool desc = ((i & k) == 0);
        ull A = d_keys[i], B = d_keys[p];
        if ((A < B) == desc) { d_keys[i] = B; d_keys[p] = A; }
    }
}

__global__ void __launch_bounds__(1024) ksort_merge(int k) {
    __shared__ ull sk[TILE];
    int base = blockIdx.x * TILE;
    for (int i = threadIdx.x; i < TILE; i += 1024) sk[i] = d_keys[base + i];
    __syncthreads();
    for (int j = TILE >> 1; j > 0; j >>= 1) {
        for (int i = threadIdx.x; i < TILE; i += 1024) {
            int p = i ^ j;
            if (p > i) {
                bool desc = (((base + i) & k) == 0);
                ull A = sk[i], B = sk[p];
                if ((A < B) == desc) { sk[i] = B; sk[p] = A; }
            }
        }
        __syncthreads();
    }
    for (int i = threadIdx.x; i < TILE; i += 1024) d_keys[base + i] = sk[i];
}

// top-K select: perm, inverse map, h2 = tanh(s) * (h @ w2)
__global__ void kselect(const float* __restrict__ w2) {
    int r = (blockIdx.x * blockDim.x + threadIdx.x) >> 5;
    if (r >= KK) return;
    int lane = threadIdx.x & 31;
    ull key = d_keys[r];
    int idx = (int)(~(unsigned)(key & 0xFFFFFFFFull));
    if (lane == 0) { d_nidx[idx] = r; d_perm[r] = idx; }
    if (lane < NCLS) {
        float th = tanhf(d_s[idx]);
        float acc = 0.f;
#pragma unroll
        for (int j = 0; j < HID; j++)
            acc += d_h[idx * HID + j] * w2[j * NCLS + lane];
        d_h2[r * NCLS + lane] = th * acc;
    }
}

// surviving-degree of kept nodes; pre-scale h2 rows by dinv2
__global__ void kdeg2() {
    int r = (blockIdx.x * blockDim.x + threadIdx.x) >> 5;
    if (r >= KK) return;
    int lane = threadIdx.x & 31;
    int i = d_perm[r];
    int st = d_rowptr[i], en = d_rowptr[i + 1];
    int cnt = 0;
    for (int e = st + lane; e < en; e += 32) cnt += (d_nidx[d_csr[e]] >= 0);
#pragma unroll
    for (int o = 16; o; o >>= 1) cnt += __shfl_xor_sync(0xFFFFFFFFu, cnt, o);
    float d2 = (float)(1.0 / sqrt((double)(cnt + 1)));
    if (lane == 0) d_dinv2[r] = d2;
    if (lane < NCLS) d_h2[r * NCLS + lane] *= d2;
}

// conv2: lane-parallel edge gather + relu + log_softmax
__global__ void kconv2(const float* __restrict__ b2, float* __restrict__ out) {
    __shared__ float red[8][NCLS];
    int r = (blockIdx.x * blockDim.x + threadIdx.x) >> 5;
    if (r >= KK) return;
    int lane = threadIdx.x & 31, wip = (threadIdx.x >> 5) & 7;
    int i = d_perm[r];
    int st = d_rowptr[i], en = d_rowptr[i + 1];
    float acc[NCLS];
#pragma unroll
    for (int c = 0; c < NCLS; c++) acc[c] = 0.f;
    for (int e = st + lane; e < en; e += 32) {
        int n0 = d_nidx[d_csr[e]];
        if (n0 >= 0) {
            const float* row = d_h2 + n0 * NCLS;
#pragma unroll
            for (int c = 0; c < NCLS; c++) acc[c] += row[c];
        }
    }
#pragma unroll
    for (int c = 0; c < NCLS; c++)
#pragma unroll
        for (int o = 16; o; o >>= 1)
            acc[c] += __shfl_xor_sync(0xFFFFFFFFu, acc[c], o);
    if (lane == 0) {
#pragma unroll
        for (int c = 0; c < NCLS; c++) red[wip][c] = acc[c];
    }
    __syncwarp();
    bool act = lane < NCLS;
    float v = act
        ? fmaxf(d_dinv2[r] * (red[wip][lane] + d_h2[r * NCLS + lane]) + b2[lane], 0.f)
        : -1e30f;
    float m = v;
#pragma unroll
    for (int o = 8; o; o >>= 1)
        m = fmaxf(m, __shfl_xor_sync(0xFFFFFFFFu, m, o, 16));
    float ex = act ? expf(v - m) : 0.f;
#pragma unroll
    for (int o = 8; o; o >>= 1)
        ex += __shfl_xor_sync(0xFFFFFFFFu, ex, o, 16);
    if (act) out[r * NCLS + lane] = v - m - logf(ex);
}

extern "C" void kernel_launch(void* const* d_in, const int* in_sizes, int n_in,
                              void* d_out, int out_size) {
    const float* x  = (const float*)d_in[0];
    const int*   ei = (const int*)d_in[1];
    const float* w1 = (const float*)d_in[2];
    const float* b1 = (const float*)d_in[3];
    const float* pw1 = (const float*)d_in[4];
    const float* pw2 = (const float*)d_in[5];
    const float* pb = (const float*)d_in[6];
    const float* w2 = (const float*)d_in[7];
    const float* b2 = (const float*)d_in[8];
    float* out = (float*)d_out;

    kinit<<<SSIZE / 256, 256>>>();
    kgemm1<<<NN / 16, 256>>>(x, w1);
    kcount<<<EE / 256, 256>>>(ei);
    kscanA<<<NBLK, SBLK>>>();
    kscanB<<<1, 128>>>();
    kscanC<<<NBLK, SBLK>>>();
    kscatter<<<EE / 256, 256>>>(ei);
    kconv1<<<NN * 32 / 256, 256>>>(b1, pw1, pw2, pb);
    kpool<<<NN * 32 / 256, 256>>>();

    ksort_init<<<SSIZE / TILE, 1024>>>();
    for (int k = TILE * 2; k <= SSIZE; k <<= 1) {
        for (int j = k >> 1; j >= TILE; j >>= 1)
            ksort_global<<<SSIZE / 256, 256>>>(j, k);
        ksort_merge<<<SSIZE / TILE, 1024>>>(k);
    }

    kselect<<<KK * 32 / 256, 256>>>(w2);
    kdeg2<<<KK * 32 / 256, 256>>>();
    kconv2<<<KK * 32 / 256, 256>>>(b2, out);
}

// round 5
// speedup vs baseline: 7.3641x; 5.7163x over previous
#include <cuda_runtime.h>
#include <math.h>

#define NN 100000
#define EE 3200000
#define HID 16
#define NCLS 10
#define KK 50000
#define SSIZE 131072
#define TILE 4096
#define SBLK 1024
#define NBLK 98   // ceil(100000/1024)

typedef unsigned long long ull;

__device__ float  d_h0[NN * HID];
__device__ float  d_h[NN * HID];
__device__ int    d_cnt[NN];
__device__ int    d_rowptr[NN + 1];
__device__ int    d_cursor[NN];
__device__ float  d_dinv[NN];
__device__ int    d_csr[EE];
__device__ float  d_spart[NN];
__device__ float  d_t2[NN];
__device__ float  d_s[NN];
__device__ ull    d_keys[SSIZE];
__device__ int    d_nidx[NN];
__device__ int    d_perm[KK];
__device__ float  d_h2[KK * NCLS];
__device__ float  d_dinv2[KK];
__device__ int    d_bsum[NBLK];
__device__ int    d_boff[NBLK];

// Kahan compensated add (safe under FMA contraction: no mul inside)
__device__ __forceinline__ void kadd(float& s, float& c, float v) {
    float y = v - c;
    float t = s + y;
    c = (t - s) - y;
    s = t;
}

// accurate fp32 rsqrt: hardware approx + one Newton step
__device__ __forceinline__ float rsqrt_acc(float x) {
    float r = rsqrtf(x);
    return r * (1.5f - 0.5f * x * r * r);
}

__global__ void kinit() {
    int i = blockIdx.x * blockDim.x + threadIdx.x;
    if (i < SSIZE) d_keys[i] = 0ull;
    if (i < NN) { d_cnt[i] = 0; d_nidx[i] = -1; }
}

// h0 = x @ w1, fp32 with 4 split accumulators. 16x16 out per 256-thread block.
__global__ void kgemm1(const float* __restrict__ x, const float* __restrict__ w1) {
    __shared__ __align__(16) float xs[16 * 128];
    __shared__ float ws[128 * 16];
    int t = threadIdx.x;
    for (int i = t; i < 2048; i += 256) ws[i] = w1[i];
    const float4* xg4 = (const float4*)(x + (size_t)blockIdx.x * 16 * 128);
    float4* xs4 = (float4*)xs;
    for (int i = t; i < 512; i += 256) xs4[i] = xg4[i];
    __syncthreads();
    int r = t >> 4, c = t & 15;
    float a0 = 0.f, a1 = 0.f, a2 = 0.f, a3 = 0.f;
#pragma unroll
    for (int k = 0; k < 32; k++) {
        a0 += xs[r * 128 + k      ] * ws[(k      ) * 16 + c];
        a1 += xs[r * 128 + k + 32 ] * ws[(k + 32 ) * 16 + c];
        a2 += xs[r * 128 + k + 64 ] * ws[(k + 64 ) * 16 + c];
        a3 += xs[r * 128 + k + 96 ] * ws[(k + 96 ) * 16 + c];
    }
    d_h0[(size_t)(blockIdx.x * 16 + r) * HID + c] = (a0 + a1) + (a2 + a3);
}

__global__ void kcount(const int* __restrict__ ei) {
    int e = blockIdx.x * blockDim.x + threadIdx.x;
    if (e < EE) atomicAdd(&d_cnt[ei[EE + e]], 1);
}

// ---- decoupled scan: A) block sums  B) scan block sums  C) local scan+offset
__global__ void __launch_bounds__(SBLK) kscanA() {
    __shared__ int ws[32];
    int i = blockIdx.x * SBLK + threadIdx.x;
    int lane = threadIdx.x & 31, wd = threadIdx.x >> 5;
    int v = (i < NN) ? d_cnt[i] : 0;
    int s = v;
#pragma unroll
    for (int o = 16; o; o >>= 1) s += __shfl_xor_sync(0xFFFFFFFFu, s, o);
    if (lane == 0) ws[wd] = s;
    __syncthreads();
    if (wd == 0) {
        int s2 = ws[lane];
#pragma unroll
        for (int o = 16; o; o >>= 1) s2 += __shfl_xor_sync(0xFFFFFFFFu, s2, o);
        if (lane == 0) d_bsum[blockIdx.x] = s2;
    }
}

__global__ void kscanB() {
    __shared__ int sm[128];
    int t = threadIdx.x;
    int v = (t < NBLK) ? d_bsum[t] : 0;
    sm[t] = v;
    __syncthreads();
    for (int o = 1; o < 128; o <<= 1) {
        int y = (t >= o) ? sm[t - o] : 0;
        __syncthreads();
        sm[t] += y;
        __syncthreads();
    }
    if (t < NBLK) d_boff[t] = sm[t] - v;
    if (t == NBLK - 1) d_rowptr[NN] = sm[t];
}

__global__ void __launch_bounds__(SBLK) kscanC() {
    __shared__ int ws[32];
    int i = blockIdx.x * SBLK + threadIdx.x;
    int lane = threadIdx.x & 31, wd = threadIdx.x >> 5;
    int v = (i < NN) ? d_cnt[i] : 0;
    int xv = v;
#pragma unroll
    for (int o = 1; o < 32; o <<= 1) {
        int y = __shfl_up_sync(0xFFFFFFFFu, xv, o);
        if (lane >= o) xv += y;
    }
    if (lane == 31) ws[wd] = xv;
    __syncthreads();
    if (wd == 0) {
        int s2 = ws[lane];
#pragma unroll
        for (int o = 1; o < 32; o <<= 1) {
            int y = __shfl_up_sync(0xFFFFFFFFu, s2, o);
            if (lane >= o) s2 += y;
        }
        ws[lane] = s2;
    }
    __syncthreads();
    int excl = xv - v + (wd > 0 ? ws[wd - 1] : 0) + d_boff[blockIdx.x];
    if (i < NN) {
        d_rowptr[i] = excl;
        d_cursor[i] = excl;
        d_dinv[i] = rsqrt_acc((float)(v + 1));
    }
}

__global__ void kscatter(const int* __restrict__ ei) {
    int e = blockIdx.x * blockDim.x + threadIdx.x;
    if (e < EE) {
        int s = ei[e];
        int d = ei[EE + e];
        d_csr[atomicAdd(&d_cursor[d], 1)] = s;
    }
}

// conv1 (+relu) fp32 Kahan accumulation, 4-way unrolled; score linear terms
__global__ void kconv1(const float* __restrict__ b1, const float* __restrict__ pw1,
                       const float* __restrict__ pw2, const float* __restrict__ pb) {
    int gw = (blockIdx.x * blockDim.x + threadIdx.x) >> 5;
    if (gw >= NN) return;
    int lane = threadIdx.x & 31, half = lane >> 4, ch = lane & 15;
    int st = d_rowptr[gw], en = d_rowptr[gw + 1];
    float s0a = 0.f, c0a = 0.f, s1a = 0.f, c1a = 0.f;
    float s2a = 0.f, c2a = 0.f, s3a = 0.f, c3a = 0.f;
    int e = st + half;
    for (; e + 6 < en; e += 8) {
        int n0 = d_csr[e], n1 = d_csr[e + 2], n2 = d_csr[e + 4], n3 = d_csr[e + 6];
        kadd(s0a, c0a, d_dinv[n0] * d_h0[n0 * HID + ch]);
        kadd(s1a, c1a, d_dinv[n1] * d_h0[n1 * HID + ch]);
        kadd(s2a, c2a, d_dinv[n2] * d_h0[n2 * HID + ch]);
        kadd(s3a, c3a, d_dinv[n3] * d_h0[n3 * HID + ch]);
    }
    for (; e < en; e += 2) {
        int n0 = d_csr[e];
        kadd(s0a, c0a, d_dinv[n0] * d_h0[n0 * HID + ch]);
    }
    // combine 4 Kahan accumulators
    kadd(s0a, c0a, s1a); kadd(s0a, c0a, -c1a);
    kadd(s0a, c0a, s2a); kadd(s0a, c0a, -c2a);
    kadd(s0a, c0a, s3a); kadd(s0a, c0a, -c3a);
    // combine across the two halves
    float os = __shfl_xor_sync(0xFFFFFFFFu, s0a, 16);
    float oc = __shfl_xor_sync(0xFFFFFFFFu, c0a, 16);
    kadd(s0a, c0a, os); kadd(s0a, c0a, -oc);
    float a = s0a - c0a;
    float degf = (float)(en - st + 1);
    float hv = d_dinv[gw] * a + d_h0[gw * HID + ch] / degf + b1[ch];
    hv = fmaxf(hv, 0.f);
    if (half == 0) d_h[gw * HID + ch] = hv;
    float u1 = hv * pw1[ch];
    float u2 = hv * pw2[ch];
#pragma unroll
    for (int o = 8; o; o >>= 1) {
        u1 += __shfl_xor_sync(0xFFFFFFFFu, u1, o);
        u2 += __shfl_xor_sync(0xFFFFFFFFu, u2, o);
    }
    if (lane == 0) { d_spart[gw] = u1 + pb[0]; d_t2[gw] = u2; }
}

// score = spart + sum_{in-neighbors} t2 (Kahan); build sort key
__global__ void kpool() {
    int gw = (blockIdx.x * blockDim.x + threadIdx.x) >> 5;
    if (gw >= NN) return;
    int lane = threadIdx.x & 31;
    int st = d_rowptr[gw], en = d_rowptr[gw + 1];
    float sum = 0.f, comp = 0.f;
    for (int e = st + lane; e < en; e += 32) kadd(sum, comp, d_t2[d_csr[e]]);
#pragma unroll
    for (int o = 16; o; o >>= 1) {
        float os = __shfl_xor_sync(0xFFFFFFFFu, sum, o);
        float oc = __shfl_xor_sync(0xFFFFFFFFu, comp, o);
        kadd(sum, comp, os); kadd(sum, comp, -oc);
    }
    if (lane == 0) {
        float sv = d_spart[gw] + (sum - comp);
        d_s[gw] = sv;
        unsigned u = __float_as_uint(sv);
        u = (u & 0x80000000u) ? ~u : (u | 0x80000000u);
        d_keys[gw] = ((ull)u << 32) | (ull)(~(unsigned)gw);
    }
}

// bitonic sort, descending, SSIZE unique keys
__global__ void __launch_bounds__(1024) ksort_init() {
    __shared__ ull sk[TILE];
    int base = blockIdx.x * TILE;
    for (int i = threadIdx.x; i < TILE; i += 1024) sk[i] = d_keys[base + i];
    __syncthreads();
    for (int k = 2; k <= TILE; k <<= 1)
        for (int j = k >> 1; j > 0; j >>= 1) {
            for (int i = threadIdx.x; i < TILE; i += 1024) {
                int p = i ^ j;
                if (p > i) {
                    bool desc = (((base + i) & k) == 0);
                    ull A = sk[i], B = sk[p];
                    if ((A < B) == desc) { sk[i] = B; sk[p] = A; }
                }
            }
            __syncthreads();
        }
    for (int i = threadIdx.x; i < TILE; i += 1024) d_keys[base + i] = sk[i];
}

__global__ void ksort_global(int j, int k) {
    int i = blockIdx.x * blockDim.x + threadIdx.x;
    int p = i ^ j;
    if (p > i && p < SSIZE) {
        bool desc = ((i & k) == 0);
        ull A = d_keys[i], B = d_keys[p];
        if ((A < B) == desc) { d_keys[i] = B; d_keys[p] = A; }
    }
}

__global__ void __launch_bounds__(1024) ksort_merge(int k) {
    __shared__ ull sk[TILE];
    int base = blockIdx.x * TILE;
    for (int i = threadIdx.x; i < TILE; i += 1024) sk[i] = d_keys[base + i];
    __syncthreads();
    for (int j = TILE >> 1; j > 0; j >>= 1) {
        for (int i = threadIdx.x; i < TILE; i += 1024) {
            int p = i ^ j;
            if (p > i) {
                bool desc = (((base + i) & k) == 0);
                ull A = sk[i], B = sk[p];
                if ((A < B) == desc) { sk[i] = B; sk[p] = A; }
            }
        }
        __syncthreads();
    }
    for (int i = threadIdx.x; i < TILE; i += 1024) d_keys[base + i] = sk[i];
}

// top-K select: perm, inverse map, h2 = tanh(s) * (h @ w2)
__global__ void kselect(const float* __restrict__ w2) {
    int r = (blockIdx.x * blockDim.x + threadIdx.x) >> 5;
    if (r >= KK) return;
    int lane = threadIdx.x & 31;
    ull key = d_keys[r];
    int idx = (int)(~(unsigned)(key & 0xFFFFFFFFull));
    if (lane == 0) { d_nidx[idx] = r; d_perm[r] = idx; }
    if (lane < NCLS) {
        float th = tanhf(d_s[idx]);
        float acc = 0.f;
#pragma unroll
        for (int j = 0; j < HID; j++)
            acc += d_h[idx * HID + j] * w2[j * NCLS + lane];
        d_h2[r * NCLS + lane] = th * acc;
    }
}

// surviving-degree of kept nodes; pre-scale h2 rows by dinv2
__global__ void kdeg2() {
    int r = (blockIdx.x * blockDim.x + threadIdx.x) >> 5;
    if (r >= KK) return;
    int lane = threadIdx.x & 31;
    int i = d_perm[r];
    int st = d_rowptr[i], en = d_rowptr[i + 1];
    int cnt = 0;
    for (int e = st + lane; e < en; e += 32) cnt += (d_nidx[d_csr[e]] >= 0);
#pragma unroll
    for (int o = 16; o; o >>= 1) cnt += __shfl_xor_sync(0xFFFFFFFFu, cnt, o);
    float d2 = rsqrt_acc((float)(cnt + 1));
    if (lane == 0) d_dinv2[r] = d2;
    if (lane < NCLS) d_h2[r * NCLS + lane] *= d2;
}

// conv2: lane-parallel edge gather + relu + log_softmax
__global__ void kconv2(const float* __restrict__ b2, float* __restrict__ out) {
    __shared__ float red[8][NCLS];
    int r = (blockIdx.x * blockDim.x + threadIdx.x) >> 5;
    if (r >= KK) return;
    int lane = threadIdx.x & 31, wip = (threadIdx.x >> 5) & 7;
    int i = d_perm[r];
    int st = d_rowptr[i], en = d_rowptr[i + 1];
    float acc[NCLS];
#pragma unroll
    for (int c = 0; c < NCLS; c++) acc[c] = 0.f;
    for (int e = st + lane; e < en; e += 32) {
        int n0 = d_nidx[d_csr[e]];
        if (n0 >= 0) {
            const float* row = d_h2 + n0 * NCLS;
#pragma unroll
            for (int c = 0; c < NCLS; c++) acc[c] += row[c];
        }
    }
#pragma unroll
    for (int c = 0; c < NCLS; c++)
#pragma unroll
        for (int o = 16; o; o >>= 1)
            acc[c] += __shfl_xor_sync(0xFFFFFFFFu, acc[c], o);
    if (lane == 0) {
#pragma unroll
        for (int c = 0; c < NCLS; c++) red[wip][c] = acc[c];
    }
    __syncwarp();
    bool act = lane < NCLS;
    float v = act
        ? fmaxf(d_dinv2[r] * (red[wip][lane] + d_h2[r * NCLS + lane]) + b2[lane], 0.f)
        : -1e30f;
    float m = v;
#pragma unroll
    for (int o = 8; o; o >>= 1)
        m = fmaxf(m, __shfl_xor_sync(0xFFFFFFFFu, m, o, 16));
    float ex = act ? expf(v - m) : 0.f;
#pragma unroll
    for (int o = 8; o; o >>= 1)
        ex += __shfl_xor_sync(0xFFFFFFFFu, ex, o, 16);
    if (act) out[r * NCLS + lane] = v - m - logf(ex);
}

extern "C" void kernel_launch(void* const* d_in, const int* in_sizes, int n_in,
                              void* d_out, int out_size) {
    const float* x  = (const float*)d_in[0];
    const int*   ei = (const int*)d_in[1];
    const float* w1 = (const float*)d_in[2];
    const float* b1 = (const float*)d_in[3];
    const float* pw1 = (const float*)d_in[4];
    const float* pw2 = (const float*)d_in[5];
    const float* pb = (const float*)d_in[6];
    const float* w2 = (const float*)d_in[7];
    const float* b2 = (const float*)d_in[8];
    float* out = (float*)d_out;

    kinit<<<SSIZE / 256, 256>>>();
    kcount<<<EE / 256, 256>>>(ei);
    kscanA<<<NBLK, SBLK>>>();
    kgemm1<<<NN / 16, 256>>>(x, w1);     // slot 4: gets profiled
    kscanB<<<1, 128>>>();
    kscanC<<<NBLK, SBLK>>>();
    kscatter<<<EE / 256, 256>>>(ei);
    kconv1<<<NN * 32 / 256, 256>>>(b1, pw1, pw2, pb);
    kpool<<<NN * 32 / 256, 256>>>();

    ksort_init<<<SSIZE / TILE, 1024>>>();
    for (int k = TILE * 2; k <= SSIZE; k <<= 1) {
        for (int j = k >> 1; j >= TILE; j >>= 1)
            ksort_global<<<SSIZE / 256, 256>>>(j, k);
        ksort_merge<<<SSIZE / TILE, 1024>>>(k);
    }

    kselect<<<KK * 32 / 256, 256>>>(w2);
    kdeg2<<<KK * 32 / 256, 256>>>();
    kconv2<<<KK * 32 / 256, 256>>>(b2, out);
}

// round 6
// speedup vs baseline: 7.8436x; 1.0651x over previous
#include <cuda_runtime.h>
#include <math.h>

#define NN 100000
#define EE 3200000
#define HID 16
#define NCLS 10
#define KK 50000
#define SSIZE 131072
#define TILE 4096
#define SBLK 1024
#define NBLK 98   // ceil(100000/1024)

typedef unsigned long long ull;

__device__ float  d_h0[NN * HID];
__device__ float  d_h[NN * HID];
__device__ int    d_cnt[NN];
__device__ int    d_rowptr[NN + 1];
__device__ int    d_cursor[NN];
__device__ float  d_dinv[NN];
__device__ int    d_csr[EE];
__device__ float  d_spart[NN];
__device__ float  d_t2[NN];
__device__ float  d_s[NN];
__device__ ull    d_keys[SSIZE];
__device__ int    d_nidx[NN];
__device__ int    d_perm[KK];
__device__ float  d_h2[KK * NCLS];
__device__ float  d_dinv2[KK];
__device__ int    d_bsum[NBLK];
__device__ int    d_boff[NBLK];

// Kahan compensated add (safe under FMA contraction: no mul inside)
__device__ __forceinline__ void kadd(float& s, float& c, float v) {
    float y = v - c;
    float t = s + y;
    c = (t - s) - y;
    s = t;
}

// accurate fp32 rsqrt: hardware approx + one Newton step
__device__ __forceinline__ float rsqrt_acc(float x) {
    float r = rsqrtf(x);
    return r * (1.5f - 0.5f * x * r * r);
}

__global__ void kinit() {
    int i = blockIdx.x * blockDim.x + threadIdx.x;
    if (i < SSIZE) d_keys[i] = 0ull;
    if (i < NN) { d_cnt[i] = 0; d_nidx[i] = -1; }
}

// h0 = x @ w1. One thread per node: x row streamed via LDG.128,
// w rows via warp-uniform LDS.128 broadcast, 16 register accumulators.
__global__ void __launch_bounds__(256) kgemm1(const float* __restrict__ x,
                                              const float* __restrict__ w1) {
    __shared__ __align__(16) float ws[128 * 16];
    int t = threadIdx.x;
    for (int i = t; i < 512; i += 256)
        ((float4*)ws)[i] = ((const float4*)w1)[i];
    __syncthreads();
    int n = blockIdx.x * 256 + t;
    if (n >= NN) return;
    const float4* xr = (const float4*)(x + (size_t)n * 128);
    float acc[16];
#pragma unroll
    for (int c = 0; c < 16; c++) acc[c] = 0.f;
#pragma unroll 4
    for (int kq = 0; kq < 32; kq++) {
        float4 xv = xr[kq];
        float xk[4] = {xv.x, xv.y, xv.z, xv.w};
#pragma unroll
        for (int j = 0; j < 4; j++) {
            const float4* wr = (const float4*)(ws + (kq * 4 + j) * 16);
            float4 w0 = wr[0], w1v = wr[1], w2v = wr[2], w3v = wr[3];
            acc[0]  += xk[j] * w0.x;  acc[1]  += xk[j] * w0.y;
            acc[2]  += xk[j] * w0.z;  acc[3]  += xk[j] * w0.w;
            acc[4]  += xk[j] * w1v.x; acc[5]  += xk[j] * w1v.y;
            acc[6]  += xk[j] * w1v.z; acc[7]  += xk[j] * w1v.w;
            acc[8]  += xk[j] * w2v.x; acc[9]  += xk[j] * w2v.y;
            acc[10] += xk[j] * w2v.z; acc[11] += xk[j] * w2v.w;
            acc[12] += xk[j] * w3v.x; acc[13] += xk[j] * w3v.y;
            acc[14] += xk[j] * w3v.z; acc[15] += xk[j] * w3v.w;
        }
    }
    float4* o = (float4*)(d_h0 + (size_t)n * HID);
#pragma unroll
    for (int q = 0; q < 4; q++)
        o[q] = make_float4(acc[q * 4], acc[q * 4 + 1], acc[q * 4 + 2], acc[q * 4 + 3]);
}

__global__ void kcount(const int* __restrict__ ei) {
    int e4 = blockIdx.x * blockDim.x + threadIdx.x;
    int4 d = ((const int4*)(ei + EE))[e4];
    atomicAdd(&d_cnt[d.x], 1);
    atomicAdd(&d_cnt[d.y], 1);
    atomicAdd(&d_cnt[d.z], 1);
    atomicAdd(&d_cnt[d.w], 1);
}

// ---- decoupled scan: A) block sums  B) scan block sums  C) local scan+offset
__global__ void __launch_bounds__(SBLK) kscanA() {
    __shared__ int ws[32];
    int i = blockIdx.x * SBLK + threadIdx.x;
    int lane = threadIdx.x & 31, wd = threadIdx.x >> 5;
    int v = (i < NN) ? d_cnt[i] : 0;
    int s = v;
#pragma unroll
    for (int o = 16; o; o >>= 1) s += __shfl_xor_sync(0xFFFFFFFFu, s, o);
    if (lane == 0) ws[wd] = s;
    __syncthreads();
    if (wd == 0) {
        int s2 = ws[lane];
#pragma unroll
        for (int o = 16; o; o >>= 1) s2 += __shfl_xor_sync(0xFFFFFFFFu, s2, o);
        if (lane == 0) d_bsum[blockIdx.x] = s2;
    }
}

__global__ void kscanB() {
    __shared__ int sm[128];
    int t = threadIdx.x;
    int v = (t < NBLK) ? d_bsum[t] : 0;
    sm[t] = v;
    __syncthreads();
    for (int o = 1; o < 128; o <<= 1) {
        int y = (t >= o) ? sm[t - o] : 0;
        __syncthreads();
        sm[t] += y;
        __syncthreads();
    }
    if (t < NBLK) d_boff[t] = sm[t] - v;
    if (t == NBLK - 1) d_rowptr[NN] = sm[t];
}

__global__ void __launch_bounds__(SBLK) kscanC() {
    __shared__ int ws[32];
    int i = blockIdx.x * SBLK + threadIdx.x;
    int lane = threadIdx.x & 31, wd = threadIdx.x >> 5;
    int v = (i < NN) ? d_cnt[i] : 0;
    int xv = v;
#pragma unroll
    for (int o = 1; o < 32; o <<= 1) {
        int y = __shfl_up_sync(0xFFFFFFFFu, xv, o);
        if (lane >= o) xv += y;
    }
    if (lane == 31) ws[wd] = xv;
    __syncthreads();
    if (wd == 0) {
        int s2 = ws[lane];
#pragma unroll
        for (int o = 1; o < 32; o <<= 1) {
            int y = __shfl_up_sync(0xFFFFFFFFu, s2, o);
            if (lane >= o) s2 += y;
        }
        ws[lane] = s2;
    }
    __syncthreads();
    int excl = xv - v + (wd > 0 ? ws[wd - 1] : 0) + d_boff[blockIdx.x];
    if (i < NN) {
        d_rowptr[i] = excl;
        d_cursor[i] = excl;
        d_dinv[i] = rsqrt_acc((float)(v + 1));
    }
}

__global__ void kscatter(const int* __restrict__ ei) {
    int e4 = blockIdx.x * blockDim.x + threadIdx.x;
    int4 s = ((const int4*)ei)[e4];
    int4 d = ((const int4*)(ei + EE))[e4];
    d_csr[atomicAdd(&d_cursor[d.x], 1)] = s.x;
    d_csr[atomicAdd(&d_cursor[d.y], 1)] = s.y;
    d_csr[atomicAdd(&d_cursor[d.z], 1)] = s.z;
    d_csr[atomicAdd(&d_cursor[d.w], 1)] = s.w;
}

// conv1 (+relu) fp32 Kahan accumulation, 4-way unrolled; score linear terms
__global__ void kconv1(const float* __restrict__ b1, const float* __restrict__ pw1,
                       const float* __restrict__ pw2, const float* __restrict__ pb) {
    int gw = (blockIdx.x * blockDim.x + threadIdx.x) >> 5;
    if (gw >= NN) return;
    int lane = threadIdx.x & 31, half = lane >> 4, ch = lane & 15;
    int st = d_rowptr[gw], en = d_rowptr[gw + 1];
    float s0a = 0.f, c0a = 0.f, s1a = 0.f, c1a = 0.f;
    float s2a = 0.f, c2a = 0.f, s3a = 0.f, c3a = 0.f;
    int e = st + half;
    for (; e + 6 < en; e += 8) {
        int n0 = d_csr[e], n1 = d_csr[e + 2], n2 = d_csr[e + 4], n3 = d_csr[e + 6];
        kadd(s0a, c0a, d_dinv[n0] * d_h0[n0 * HID + ch]);
        kadd(s1a, c1a, d_dinv[n1] * d_h0[n1 * HID + ch]);
        kadd(s2a, c2a, d_dinv[n2] * d_h0[n2 * HID + ch]);
        kadd(s3a, c3a, d_dinv[n3] * d_h0[n3 * HID + ch]);
    }
    for (; e < en; e += 2) {
        int n0 = d_csr[e];
        kadd(s0a, c0a, d_dinv[n0] * d_h0[n0 * HID + ch]);
    }
    kadd(s0a, c0a, s1a); kadd(s0a, c0a, -c1a);
    kadd(s0a, c0a, s2a); kadd(s0a, c0a, -c2a);
    kadd(s0a, c0a, s3a); kadd(s0a, c0a, -c3a);
    float os = __shfl_xor_sync(0xFFFFFFFFu, s0a, 16);
    float oc = __shfl_xor_sync(0xFFFFFFFFu, c0a, 16);
    kadd(s0a, c0a, os); kadd(s0a, c0a, -oc);
    float a = s0a - c0a;
    float degf = (float)(en - st + 1);
    float hv = d_dinv[gw] * a + d_h0[gw * HID + ch] / degf + b1[ch];
    hv = fmaxf(hv, 0.f);
    if (half == 0) d_h[gw * HID + ch] = hv;
    float u1 = hv * pw1[ch];
    float u2 = hv * pw2[ch];
#pragma unroll
    for (int o = 8; o; o >>= 1) {
        u1 += __shfl_xor_sync(0xFFFFFFFFu, u1, o);
        u2 += __shfl_xor_sync(0xFFFFFFFFu, u2, o);
    }
    if (lane == 0) { d_spart[gw] = u1 + pb[0]; d_t2[gw] = u2; }
}

// score = spart + sum_{in-neighbors} t2 (Kahan); build sort key
__global__ void kpool() {
    int gw = (blockIdx.x * blockDim.x + threadIdx.x) >> 5;
    if (gw >= NN) return;
    int lane = threadIdx.x & 31;
    int st = d_rowptr[gw], en = d_rowptr[gw + 1];
    float sum = 0.f, comp = 0.f;
    for (int e = st + lane; e < en; e += 32) kadd(sum, comp, d_t2[d_csr[e]]);
#pragma unroll
    for (int o = 16; o; o >>= 1) {
        float os = __shfl_xor_sync(0xFFFFFFFFu, sum, o);
        float oc = __shfl_xor_sync(0xFFFFFFFFu, comp, o);
        kadd(sum, comp, os); kadd(sum, comp, -oc);
    }
    if (lane == 0) {
        float sv = d_spart[gw] + (sum - comp);
        d_s[gw] = sv;
        unsigned u = __float_as_uint(sv);
        u = (u & 0x80000000u) ? ~u : (u | 0x80000000u);
        d_keys[gw] = ((ull)u << 32) | (ull)(~(unsigned)gw);
    }
}

// bitonic sort, descending, SSIZE unique keys
__global__ void __launch_bounds__(1024) ksort_init() {
    __shared__ ull sk[TILE];
    int base = blockIdx.x * TILE;
    for (int i = threadIdx.x; i < TILE; i += 1024) sk[i] = d_keys[base + i];
    __syncthreads();
    for (int k = 2; k <= TILE; k <<= 1)
        for (int j = k >> 1; j > 0; j >>= 1) {
            for (int i = threadIdx.x; i < TILE; i += 1024) {
                int p = i ^ j;
                if (p > i) {
                    bool desc = (((base + i) & k) == 0);
                    ull A = sk[i], B = sk[p];
                    if ((A < B) == desc) { sk[i] = B; sk[p] = A; }
                }
            }
            __syncthreads();
        }
    for (int i = threadIdx.x; i < TILE; i += 1024) d_keys[base + i] = sk[i];
}

// all global steps (j >= 4096) of phase k, fused. Block owns the strided set
// { m*4096 + lowbase + low : m in [0,32), low in [0,128) }  (coalesced rows)
__global__ void __launch_bounds__(1024) kcol(int k) {
    __shared__ ull sk[4096];          // [m][low] : 32 x 128
    int lowbase = blockIdx.x * 128;
    for (int idx = threadIdx.x; idx < 4096; idx += 1024) {
        int m = idx >> 7, low = idx & 127;
        sk[idx] = d_keys[m * 4096 + lowbase + low];
    }
    __syncthreads();
    int kp = k >> 12;                 // k' in units of 4096
    for (int jp = kp >> 1; jp >= 1; jp >>= 1) {
        for (int q = threadIdx.x; q < 2048; q += 1024) {
            int low = q & 127;
            int mg = q >> 7;          // 0..15
            int m = ((mg & ~(jp - 1)) << 1) | (mg & (jp - 1));
            int p = m | jp;
            bool desc = ((m & kp) == 0);
            ull A = sk[m * 128 + low], B = sk[p * 128 + low];
            if ((A < B) == desc) { sk[m * 128 + low] = B; sk[p * 128 + low] = A; }
        }
        __syncthreads();
    }
    for (int idx = threadIdx.x; idx < 4096; idx += 1024) {
        int m = idx >> 7, low = idx & 127;
        d_keys[m * 4096 + lowbase + low] = sk[idx];
    }
}

__global__ void __launch_bounds__(1024) ksort_merge(int k) {
    __shared__ ull sk[TILE];
    int base = blockIdx.x * TILE;
    for (int i = threadIdx.x; i < TILE; i += 1024) sk[i] = d_keys[base + i];
    __syncthreads();
    for (int j = TILE >> 1; j > 0; j >>= 1) {
        for (int i = threadIdx.x; i < TILE; i += 1024) {
            int p = i ^ j;
            if (p > i) {
                bool desc = (((base + i) & k) == 0);
                ull A = sk[i], B = sk[p];
                if ((A < B) == desc) { sk[i] = B; sk[p] = A; }
            }
        }
        __syncthreads();
    }
    for (int i = threadIdx.x; i < TILE; i += 1024) d_keys[base + i] = sk[i];
}

// top-K select: perm, inverse map, h2 = tanh(s) * (h @ w2)
__global__ void kselect(const float* __restrict__ w2) {
    int r = (blockIdx.x * blockDim.x + threadIdx.x) >> 5;
    if (r >= KK) return;
    int lane = threadIdx.x & 31;
    ull key = d_keys[r];
    int idx = (int)(~(unsigned)(key & 0xFFFFFFFFull));
    if (lane == 0) { d_nidx[idx] = r; d_perm[r] = idx; }
    if (lane < NCLS) {
        float th = tanhf(d_s[idx]);
        float acc = 0.f;
#pragma unroll
        for (int j = 0; j < HID; j++)
            acc += d_h[idx * HID + j] * w2[j * NCLS + lane];
        d_h2[r * NCLS + lane] = th * acc;
    }
}

// surviving-degree of kept nodes; pre-scale h2 rows by dinv2
__global__ void kdeg2() {
    int r = (blockIdx.x * blockDim.x + threadIdx.x) >> 5;
    if (r >= KK) return;
    int lane = threadIdx.x & 31;
    int i = d_perm[r];
    int st = d_rowptr[i], en = d_rowptr[i + 1];
    int cnt = 0;
    for (int e = st + lane; e < en; e += 32) cnt += (d_nidx[d_csr[e]] >= 0);
#pragma unroll
    for (int o = 16; o; o >>= 1) cnt += __shfl_xor_sync(0xFFFFFFFFu, cnt, o);
    float d2 = rsqrt_acc((float)(cnt + 1));
    if (lane == 0) d_dinv2[r] = d2;
    if (lane < NCLS) d_h2[r * NCLS + lane] *= d2;
}

// conv2: lane-parallel edge gather + relu + log_softmax
__global__ void kconv2(const float* __restrict__ b2, float* __restrict__ out) {
    __shared__ float red[8][NCLS];
    int r = (blockIdx.x * blockDim.x + threadIdx.x) >> 5;
    if (r >= KK) return;
    int lane = threadIdx.x & 31, wip = (threadIdx.x >> 5) & 7;
    int i = d_perm[r];
    int st = d_rowptr[i], en = d_rowptr[i + 1];
    float acc[NCLS];
#pragma unroll
    for (int c = 0; c < NCLS; c++) acc[c] = 0.f;
    for (int e = st + lane; e < en; e += 32) {
        int n0 = d_nidx[d_csr[e]];
        if (n0 >= 0) {
            const float* row = d_h2 + n0 * NCLS;
#pragma unroll
            for (int c = 0; c < NCLS; c++) acc[c] += row[c];
        }
    }
#pragma unroll
    for (int c = 0; c < NCLS; c++)
#pragma unroll
        for (int o = 16; o; o >>= 1)
            acc[c] += __shfl_xor_sync(0xFFFFFFFFu, acc[c], o);
    if (lane == 0) {
#pragma unroll
        for (int c = 0; c < NCLS; c++) red[wip][c] = acc[c];
    }
    __syncwarp();
    bool act = lane < NCLS;
    float v = act
        ? fmaxf(d_dinv2[r] * (red[wip][lane] + d_h2[r * NCLS + lane]) + b2[lane], 0.f)
        : -1e30f;
    float m = v;
#pragma unroll
    for (int o = 8; o; o >>= 1)
        m = fmaxf(m, __shfl_xor_sync(0xFFFFFFFFu, m, o, 16));
    float ex = act ? expf(v - m) : 0.f;
#pragma unroll
    for (int o = 8; o; o >>= 1)
        ex += __shfl_xor_sync(0xFFFFFFFFu, ex, o, 16);
    if (act) out[r * NCLS + lane] = v - m - logf(ex);
}

extern "C" void kernel_launch(void* const* d_in, const int* in_sizes, int n_in,
                              void* d_out, int out_size) {
    const float* x  = (const float*)d_in[0];
    const int*   ei = (const int*)d_in[1];
    const float* w1 = (const float*)d_in[2];
    const float* b1 = (const float*)d_in[3];
    const float* pw1 = (const float*)d_in[4];
    const float* pw2 = (const float*)d_in[5];
    const float* pb = (const float*)d_in[6];
    const float* w2 = (const float*)d_in[7];
    const float* b2 = (const float*)d_in[8];
    float* out = (float*)d_out;

    kinit<<<SSIZE / 256, 256>>>();
    kcount<<<EE / 1024, 256>>>(ei);
    kscanA<<<NBLK, SBLK>>>();
    kgemm1<<<(NN + 255) / 256, 256>>>(x, w1);   // slot 4: gets profiled
    kscanB<<<1, 128>>>();
    kscanC<<<NBLK, SBLK>>>();
    kscatter<<<EE / 1024, 256>>>(ei);
    kconv1<<<NN * 32 / 256, 256>>>(b1, pw1, pw2, pb);
    kpool<<<NN * 32 / 256, 256>>>();

    ksort_init<<<SSIZE / TILE, 1024>>>();
    for (int k = TILE * 2; k <= SSIZE; k <<= 1) {
        kcol<<<SSIZE / 4096, 1024>>>(k);
        ksort_merge<<<SSIZE / TILE, 1024>>>(k);
    }

    kselect<<<KK * 32 / 256, 256>>>(w2);
    kdeg2<<<KK * 32 / 256, 256>>>();
    kconv2<<<KK * 32 / 256, 256>>>(b2, out);
}